// round 12
// baseline (speedup 1.0000x reference)
#include <cuda_runtime.h>

#define N_RAYS   8192
#define N_SAMP   256
#define HID      64
#define OUT_ROW  261        // 3 colors + depth + missed + 256 probs
#define RPB      2          // rays per block (one warp per ray)
#define THREADS  64

__device__ __forceinline__ unsigned long long pack2(float lo, float hi) {
    unsigned long long r;
    asm("mov.b64 %0, {%1, %2};" : "=l"(r) : "f"(lo), "f"(hi));
    return r;
}
__device__ __forceinline__ void unpack2(unsigned long long v, float& lo, float& hi) {
    asm("mov.b64 {%0, %1}, %2;" : "=f"(lo), "=f"(hi) : "l"(v));
}
#define FMA2(acc, x, y) asm("fma.rn.f32x2 %0, %1, %2, %0;" : "+l"(acc) : "l"(x), "l"(y))

__device__ __forceinline__ float fast_sigmoid(float x) {
    float th;
    asm("tanh.approx.f32 %0, %1;" : "=f"(th) : "f"(0.5f * x));
    return fmaf(0.5f, th, 0.5f);
}

__global__ void __launch_bounds__(THREADS, 16)
volume_render_kernel(const float* __restrict__ ray_start,
                     const float* __restrict__ ray_dir,
                     const float* __restrict__ depth,
                     const float* __restrict__ dists,
                     const int*   __restrict__ sampled_idx,
                     const float* __restrict__ W1,
                     const float* __restrict__ b1,
                     const float* __restrict__ w_sigma,
                     const float* __restrict__ W_rgb,
                     const float* __restrict__ W_dir,
                     const float* __restrict__ b_rgb,
                     float* __restrict__ out)
{
    __shared__ ulonglong2 sAB[RPB][HID];  // .x=(a,a) .y=(b,b) per ray
    __shared__ ulonglong2 sWa[HID];       // .x=(ws,ws) .y=(wr0,wr0)
    __shared__ ulonglong2 sWb[HID];       // .x=(wr1,wr1) .y=(wr2,wr2)

    const int t    = threadIdx.x;
    const int rl   = t >> 5;      // warp id == ray slot (0..1)
    const int lane = t & 31;
    const int r    = blockIdx.x * RPB + rl;

    const float rs0 = ray_start[3*r+0], rs1 = ray_start[3*r+1], rs2 = ray_start[3*r+2];
    const float rd0 = ray_dir  [3*r+0], rd1 = ray_dir  [3*r+1], rd2 = ray_dir  [3*r+2];

    // ---- prologue: per-ray affine coeffs + splatted weights ----
    #pragma unroll
    for (int q = 0; q < 2; q++) {
        int jj = lane + 32*q;
        float w0 = W1[jj], w1 = W1[HID + jj], w2 = W1[2*HID + jj];
        float a  = fmaf(rs2, w2, fmaf(rs1, w1, fmaf(rs0, w0, b1[jj])));
        float b  = fmaf(rd2, w2, fmaf(rd1, w1, rd0 * w0));
        sAB[rl][jj] = make_ulonglong2(pack2(a, a), pack2(b, b));
    }
    {
        int jj = t;               // 64 threads cover HID exactly
        float ws = w_sigma[jj];
        float q0 = W_rgb[3*jj+0];
        float q1 = W_rgb[3*jj+1];
        float q2 = W_rgb[3*jj+2];
        sWa[jj] = make_ulonglong2(pack2(ws, ws), pack2(q0, q0));
        sWb[jj] = make_ulonglong2(pack2(q1, q1), pack2(q2, q2));
    }

    // per-ray view-dir color offsets — folded into accumulator init
    const float dc0 = fmaf(rd2, W_dir[6], fmaf(rd1, W_dir[3], fmaf(rd0, W_dir[0], b_rgb[0])));
    const float dc1 = fmaf(rd2, W_dir[7], fmaf(rd1, W_dir[4], fmaf(rd0, W_dir[1], b_rgb[1])));
    const float dc2 = fmaf(rd2, W_dir[8], fmaf(rd1, W_dir[5], fmaf(rd0, W_dir[2], b_rgb[2])));
    __syncthreads();

    // ---- load 8 depths per thread ----
    const size_t si = (size_t)r * N_SAMP + lane * 8;
    const float4 dA = *(const float4*)(depth + si);
    const float4 dB = *(const float4*)(depth + si + 4);

    unsigned long long td[4];
    td[0] = pack2(dA.x, dA.y); td[1] = pack2(dA.z, dA.w);
    td[2] = pack2(dB.x, dB.y); td[3] = pack2(dB.z, dB.w);

    unsigned long long sg[4] = {0,0,0,0};
    unsigned long long a0[4], a1[4], a2[4];
    #pragma unroll
    for (int p = 0; p < 4; p++) {
        a0[p] = pack2(dc0, dc0);
        a1[p] = pack2(dc1, dc1);
        a2[p] = pack2(dc2, dc2);
    }

    #define K_BODY(k)                                                              \
    {                                                                              \
        ulonglong2 ab = sAB[rl][k];                                                \
        ulonglong2 wa = sWa[k];                                                    \
        ulonglong2 wb = sWb[k];                                                    \
        _Pragma("unroll")                                                          \
        for (int p = 0; p < 4; p++) {                                              \
            unsigned long long h;                                                  \
            asm("fma.rn.f32x2 %0, %1, %2, %3;"                                     \
                : "=l"(h) : "l"(td[p]), "l"(ab.y), "l"(ab.x));                     \
            float hlo, hhi;                                                        \
            unpack2(h, hlo, hhi);                                                  \
            hlo = fmaxf(hlo, 0.f);                                                 \
            hhi = fmaxf(hhi, 0.f);                                                 \
            unsigned long long pr = pack2(hlo, hhi);                               \
            FMA2(sg[p], pr, wa.x);                                                 \
            FMA2(a0[p], pr, wa.y);                                                 \
            FMA2(a1[p], pr, wb.x);                                                 \
            FMA2(a2[p], pr, wb.y);                                                 \
        }                                                                          \
    }

    // first 48 hidden units
    #pragma unroll 16
    for (int k = 0; k < 48; k++) K_BODY(k)

    // prefetch epilogue inputs — latency hidden behind last 16 iterations
    const float4 xA = *(const float4*)(dists + si);
    const float4 xB = *(const float4*)(dists + si + 4);
    const int4   iA = *(const int4*)(sampled_idx + si);
    const int4   iB = *(const int4*)(sampled_idx + si + 4);

    #pragma unroll 16
    for (int k = 48; k < HID; k++) K_BODY(k)
    #undef K_BODY

    // ---- free energy + local inclusive prefix cum[1..8] ----
    float cum[9];
    cum[0] = 0.f;
    {
        const float ddv[8] = {xA.x,xA.y,xA.z,xA.w,xB.x,xB.y,xB.z,xB.w};
        const int   mkv[8] = {iA.x!=-1,iA.y!=-1,iA.z!=-1,iA.w!=-1,
                              iB.x!=-1,iB.y!=-1,iB.z!=-1,iB.w!=-1};
        #pragma unroll
        for (int p = 0; p < 4; p++) {
            float slo, shi;
            unpack2(sg[p], slo, shi);
            float f0 = mkv[2*p]   ? fmaxf(slo, 0.f) * ddv[2*p]   * 7.0f : 0.f;
            float f1 = mkv[2*p+1] ? fmaxf(shi, 0.f) * ddv[2*p+1] * 7.0f : 0.f;
            cum[2*p+1] = cum[2*p] + f0;
            cum[2*p+2] = cum[2*p+1] + f1;
        }
    }
    const float run = cum[8];

    // warp-exclusive scan of per-thread totals
    float v = run;
    #pragma unroll
    for (int o = 1; o < 32; o <<= 1) {
        float n = __shfl_up_sync(0xffffffffu, v, o);
        if (lane >= o) v += n;
    }
    const float excl = v - run;

    float* orow = out + (size_t)r * OUT_ROW;

    // ---- telescoping transmittance: prob[k] = E[k] - E[k+1] ----
    float Ep = __expf(-excl);
    const float Efirst = Ep;
    float s1 = 0.f, s2 = 0.f, s3 = 0.f, s4 = 0.f;
    #pragma unroll
    for (int p = 0; p < 4; p++) {
        float t0, t1;
        unpack2(td[p], t0, t1);
        float c00, c01; unpack2(a0[p], c00, c01);
        float c10, c11; unpack2(a1[p], c10, c11);
        float c20, c21; unpack2(a2[p], c20, c21);
        #pragma unroll
        for (int q = 0; q < 2; q++) {
            int k = 2*p + q;
            float Ek   = __expf(-(excl + cum[k+1]));
            float prob = Ep - Ek;
            Ep = Ek;
            float rr = fast_sigmoid(q ? c01 : c00);
            float gg = fast_sigmoid(q ? c11 : c10);
            float bb = fast_sigmoid(q ? c21 : c20);
            orow[5 + 8*lane + k] = prob;
            s1 = fmaf(q ? t1 : t0, prob, s1);
            s2 = fmaf(rr, prob, s2);
            s3 = fmaf(gg, prob, s3);
            s4 = fmaf(bb, prob, s4);
        }
    }
    float s0 = Efirst - Ep;   // sum of probs telescopes

    #pragma unroll
    for (int o = 16; o; o >>= 1) {
        s0 += __shfl_xor_sync(0xffffffffu, s0, o);
        s1 += __shfl_xor_sync(0xffffffffu, s1, o);
        s2 += __shfl_xor_sync(0xffffffffu, s2, o);
        s3 += __shfl_xor_sync(0xffffffffu, s3, o);
        s4 += __shfl_xor_sync(0xffffffffu, s4, o);
    }
    if (lane == 0) {
        orow[0] = s2;        // color r
        orow[1] = s3;        // color g
        orow[2] = s4;        // color b
        orow[3] = s1;        // depth
        orow[4] = 1.f - s0;  // missed
    }
}

extern "C" void kernel_launch(void* const* d_in, const int* in_sizes, int n_in,
                              void* d_out, int out_size)
{
    const float* ray_start = (const float*)d_in[0];
    const float* ray_dir   = (const float*)d_in[1];
    const float* depth     = (const float*)d_in[2];
    const float* dists     = (const float*)d_in[3];
    const int*   sidx      = (const int*)d_in[4];
    const float* W1        = (const float*)d_in[5];
    const float* b1        = (const float*)d_in[6];
    const float* w_sigma   = (const float*)d_in[7];
    const float* W_rgb     = (const float*)d_in[8];
    const float* W_dir     = (const float*)d_in[9];
    const float* b_rgb     = (const float*)d_in[10];
    float* out = (float*)d_out;

    volume_render_kernel<<<N_RAYS / RPB, THREADS>>>(
        ray_start, ray_dir, depth, dists, sidx,
        W1, b1, w_sigma, W_rgb, W_dir, b_rgb, out);
}